// round 17
// baseline (speedup 1.0000x reference)
#include <cuda_runtime.h>
#include <math.h>

// Fixed problem: B=128, T=514, D=8, H=64, L=2, IN=17, W=512, N=65536
// out: [0,524288) residuals (B,W,D) | [524288,524416) logdet (B,) | [524416,..) hist_jac (D,N,16)
#define SLOPE 0.2f
#define S 68               // row stride (floats) for act and weight tiles

#define OFF_A    0         // act ping  [128 samples][S]  ([sample][k])
#define OFF_B    8704      // act pong  [128][S]
#define OFF_WHI  17408     // weight hi plane [64][S]  (tf32-rounded fp32)
#define OFF_WLO  21760     // weight lo plane [64][S]
#define OFF_SB0  26112
#define OFF_SB1  26176
#define OFF_SB2  26240
#define OFF_SWO  26304
#define OFF_J    26368     // 8 warp logdet partials
#define OFF_FLAG 26376
#define SMEM_FLOATS 26380
#define SMEM_BYTES (SMEM_FLOATS * 4)

typedef unsigned int u32;

__device__ float g_partials[4096];   // [d][tile]
__device__ u32   g_done = 0;

__device__ __forceinline__ u32 cvtt(float x) {
    u32 r; asm("cvt.rna.tf32.f32 %0, %1;" : "=r"(r) : "f"(x)); return r;
}
__device__ __forceinline__ float uf(u32 x) { return __uint_as_float(x); }
__device__ __forceinline__ float lk(float v) { return v > 0.f ? v : v * SLOPE; }
__device__ __forceinline__ float mb(u32 m, int b) { return ((m >> b) & 1u) ? 1.f : SLOPE; }

__device__ __forceinline__ void mma8(float* d, u32 a0, u32 a1, u32 a2, u32 a3,
                                     u32 b0, u32 b1) {
    asm("mma.sync.aligned.m16n8k8.row.col.f32.tf32.tf32.f32 "
        "{%0,%1,%2,%3}, {%4,%5,%6,%7}, {%8,%9}, {%0,%1,%2,%3};"
        : "+f"(d[0]), "+f"(d[1]), "+f"(d[2]), "+f"(d[3])
        : "r"(a0), "r"(a1), "r"(a2), "r"(a3), "r"(b0), "r"(b1));
}

// D[16 samples x NT*8 outs] (+)= A[16 x NK*8] * W[NT*8 x NK*8]^T with tf32 3-term split.
// A fp32 [sample][k]; W pre-split hi/lo planes [out][k].
// Frags (m16n8k8 tf32): a0=(r,c) a1=(r+8,c) a2=(r,c+4) a3=(r+8,c+4);
//                       b0=(k=c, n=r) b1=(k=c+4, n=r);
//                       d: c0=(r,2c) c1=(r,2c+1) c2=(r+8,2c) c3=(r+8,2c+1)
template<int NT, int NK>
__device__ __forceinline__ void gemm_mma(const float* __restrict__ Ab,
                                         const float* __restrict__ whi,
                                         const float* __restrict__ wlo,
                                         int sRow, int r, int c, float* acc) {
    const float* ap = Ab + (sRow + r) * S + c;
#pragma unroll
    for (int kk = 0; kk < NK; ++kk) {
        float a0f = ap[kk * 8];
        float a1f = ap[kk * 8 + 8 * S];
        float a2f = ap[kk * 8 + 4];
        float a3f = ap[kk * 8 + 4 + 8 * S];
        u32 a0h = cvtt(a0f), a1h = cvtt(a1f), a2h = cvtt(a2f), a3h = cvtt(a3f);
        u32 a0l = cvtt(a0f - uf(a0h)), a1l = cvtt(a1f - uf(a1h));
        u32 a2l = cvtt(a2f - uf(a2h)), a3l = cvtt(a3f - uf(a3h));
#pragma unroll
        for (int t = 0; t < NT; ++t) {
            const float* wp = whi + (t * 8 + r) * S + kk * 8 + c;
            const float* wq = wlo + (t * 8 + r) * S + kk * 8 + c;
            u32 b0h = __float_as_uint(wp[0]), b1h = __float_as_uint(wp[4]);
            u32 b0l = __float_as_uint(wq[0]), b1l = __float_as_uint(wq[4]);
            mma8(acc + t * 4, a0h, a1h, a2h, a3h, b0h, b1h);
            mma8(acc + t * 4, a0l, a1l, a2l, a3l, b0h, b1h);
            mma8(acc + t * 4, a0h, a1h, a2h, a3h, b0l, b1l);
        }
    }
}

// Stage 64x64 row-major weights -> hi/lo planes, natural [out][k] (forward).
#define STAGE_NAT(SRC) do {                                                     \
    float4 pre[4];                                                              \
    _Pragma("unroll")                                                           \
    for (int q = 0; q < 4; ++q) pre[q] = ((const float4*)(SRC))[q * 256 + tid]; \
    _Pragma("unroll")                                                           \
    for (int q = 0; q < 4; ++q) {                                               \
        int i4 = q * 256 + tid; int row = i4 >> 4, c4 = (i4 & 15) * 4;          \
        float4 v = pre[q]; float4 H, L;                                         \
        H.x = uf(cvtt(v.x)); L.x = uf(cvtt(v.x - H.x));                         \
        H.y = uf(cvtt(v.y)); L.y = uf(cvtt(v.y - H.y));                         \
        H.z = uf(cvtt(v.z)); L.z = uf(cvtt(v.z - H.z));                         \
        H.w = uf(cvtt(v.w)); L.w = uf(cvtt(v.w - H.w));                         \
        *(float4*)(sm + OFF_WHI + row * S + c4) = H;                            \
        *(float4*)(sm + OFF_WLO + row * S + c4) = L;                            \
    } } while (0)

// Stage 64x64 row-major weights TRANSPOSED -> hi/lo planes (backward).
#define STAGE_TR(SRC) do {                                                      \
    float4 pre[4];                                                              \
    _Pragma("unroll")                                                           \
    for (int q = 0; q < 4; ++q) pre[q] = ((const float4*)(SRC))[q * 256 + tid]; \
    _Pragma("unroll")                                                           \
    for (int q = 0; q < 4; ++q) {                                               \
        int i4 = q * 256 + tid; int row = i4 >> 4, c4 = (i4 & 15) * 4;          \
        float vv[4] = {pre[q].x, pre[q].y, pre[q].z, pre[q].w};                 \
        _Pragma("unroll")                                                       \
        for (int j = 0; j < 4; ++j) {                                           \
            float h = uf(cvtt(vv[j]));                                          \
            sm[OFF_WHI + (c4 + j) * S + row] = h;                               \
            sm[OFF_WLO + (c4 + j) * S + row] = uf(cvtt(vv[j] - h));             \
        }                                                                       \
    } } while (0)

// Forward epilogue: leaky + mask record + store pairs to DST ([sample][out]).
#define EPI_FWD(DST, MASK)                                                      \
    _Pragma("unroll")                                                           \
    for (int t = 0; t < 8; ++t) {                                               \
        float v0 = acc[t * 4], v1 = acc[t * 4 + 1];                             \
        float v2 = acc[t * 4 + 2], v3 = acc[t * 4 + 3];                         \
        MASK |= ((u32)(v0 > 0.f) << (t * 4)) | ((u32)(v1 > 0.f) << (t * 4 + 1)) \
              | ((u32)(v2 > 0.f) << (t * 4 + 2)) | ((u32)(v3 > 0.f) << (t * 4 + 3)); \
        int n0 = t * 8 + 2 * c;                                                 \
        *(float2*)(sm + (DST) + (sRow + r) * S + n0)     = make_float2(lk(v0), lk(v1)); \
        *(float2*)(sm + (DST) + (sRow + r + 8) * S + n0) = make_float2(lk(v2), lk(v3)); \
    }

// Backward epilogue: multiply by saved mask, store to DST.
#define EPI_BWD(DST, MASK)                                                      \
    _Pragma("unroll")                                                           \
    for (int t = 0; t < 8; ++t) {                                               \
        int n0 = t * 8 + 2 * c;                                                 \
        *(float2*)(sm + (DST) + (sRow + r) * S + n0) =                          \
            make_float2(acc[t * 4] * mb(MASK, t * 4),                           \
                        acc[t * 4 + 1] * mb(MASK, t * 4 + 1));                  \
        *(float2*)(sm + (DST) + (sRow + r + 8) * S + n0) =                      \
            make_float2(acc[t * 4 + 2] * mb(MASK, t * 4 + 2),                   \
                        acc[t * 4 + 3] * mb(MASK, t * 4 + 3));                  \
    }

#define INIT_BIAS(SB)                                                           \
    _Pragma("unroll")                                                           \
    for (int t = 0; t < 8; ++t) {                                               \
        float2 bb = *(const float2*)(sm + (SB) + t * 8 + 2 * c);                \
        acc[t * 4] = bb.x; acc[t * 4 + 1] = bb.y;                               \
        acc[t * 4 + 2] = bb.x; acc[t * 4 + 3] = bb.y;                           \
    }
#define INIT_Z()                                                                \
    _Pragma("unroll") for (int i = 0; i < 32; ++i) acc[i] = 0.f;

__global__ void __launch_bounds__(256, 2)
mlp_mma_kernel(const float* __restrict__ x,
               const float* __restrict__ W0, const float* __restrict__ b0,
               const float* __restrict__ W1, const float* __restrict__ b1,
               const float* __restrict__ W2, const float* __restrict__ b2,
               const float* __restrict__ Wo, const float* __restrict__ bo,
               float* __restrict__ out)
{
    extern __shared__ float sm[];
    const int tid  = threadIdx.x;     // 256 threads = 8 warps
    const int lane = tid & 31;
    const int warp = tid >> 5;
    const int r    = lane >> 2;       // fragment row group
    const int c    = lane & 3;        // fragment col group
    const int sRow = warp * 16;       // warp's 16-sample block
    const int tile = blockIdx.x;      // 512 tiles
    const int d    = blockIdx.y;
    const float bo_d = bo[d];

    // ---- phase 1: stage X -> ACT_A ([sample][k], cols 16..23 = {x16,0..}), W0 hi/lo, biases ----
    {
        const int s = tid >> 1, half = tid & 1;
        const int n = tile * 128 + s;
        const float* xb = x + (size_t)((n >> 9) * 514 + (n & 511)) * 8;
        float* Ar = sm + OFF_A + s * S;
        if (half == 0) {
            *(float4*)(Ar + 0) = *(const float4*)(xb);
            *(float4*)(Ar + 4) = *(const float4*)(xb + 4);
        } else {
            *(float4*)(Ar + 8)  = *(const float4*)(xb + 8);
            *(float4*)(Ar + 12) = *(const float4*)(xb + 12);
            *(float4*)(Ar + 16) = make_float4(xb[16 + d], 0.f, 0.f, 0.f);
            *(float4*)(Ar + 20) = make_float4(0.f, 0.f, 0.f, 0.f);
        }
    }
    for (int i = tid; i < 448; i += 256) {          // zero W cols 17..23
        int row = i / 7, cc = 17 + (i - 7 * row);
        sm[OFF_WHI + row * S + cc] = 0.f;
        sm[OFF_WLO + row * S + cc] = 0.f;
    }
    for (int i = tid; i < 1088; i += 256) {         // W0 natural [h][k] split
        int h = i / 17, k = i - 17 * h;
        float v = W0[d * 1088 + i];
        float hh = uf(cvtt(v));
        sm[OFF_WHI + h * S + k] = hh;
        sm[OFF_WLO + h * S + k] = uf(cvtt(v - hh));
    }
    if (tid < 64) {
        sm[OFF_SB0 + tid] = b0[d * 64 + tid];
        sm[OFF_SB1 + tid] = b1[d * 64 + tid];
        sm[OFF_SB2 + tid] = b2[d * 64 + tid];
        sm[OFF_SWO + tid] = Wo[d * 64 + tid];
    }
    __syncthreads();

    float acc[32];
    u32 m0 = 0, m1 = 0;

    // ---- L0: A(X) @ W0^T -> act0 in B ----
    INIT_BIAS(OFF_SB0);
    gemm_mma<8, 3>(sm + OFF_A, sm + OFF_WHI, sm + OFF_WLO, sRow, r, c, acc);
    EPI_FWD(OFF_B, m0);
    __syncthreads();

    STAGE_NAT(W1 + d * 4096);
    __syncthreads();

    // ---- L1: B @ W1^T -> act1 in A ----
    INIT_BIAS(OFF_SB1);
    gemm_mma<8, 8>(sm + OFF_B, sm + OFF_WHI, sm + OFF_WLO, sRow, r, c, acc);
    EPI_FWD(OFF_A, m1);
    __syncthreads();

    STAGE_NAT(W2 + d * 4096);
    __syncthreads();

    // ---- L2 + head: A @ W2^T; residual; g = Wo*m2 -> B ----
    INIT_BIAS(OFF_SB2);
    gemm_mma<8, 8>(sm + OFF_A, sm + OFF_WHI, sm + OFF_WLO, sRow, r, c, acc);
    {
        float os0 = 0.f, os1 = 0.f;
#pragma unroll
        for (int t = 0; t < 8; ++t) {
            float2 wo = *(const float2*)(sm + OFF_SWO + t * 8 + 2 * c);
            float v0 = acc[t * 4], v1 = acc[t * 4 + 1];
            float v2 = acc[t * 4 + 2], v3 = acc[t * 4 + 3];
            float g0 = wo.x * (v0 > 0.f ? 1.f : SLOPE);
            float g1 = wo.y * (v1 > 0.f ? 1.f : SLOPE);
            float g2 = wo.x * (v2 > 0.f ? 1.f : SLOPE);
            float g3 = wo.y * (v3 > 0.f ? 1.f : SLOPE);
            os0 = fmaf(g0, v0, fmaf(g1, v1, os0));
            os1 = fmaf(g2, v2, fmaf(g3, v3, os1));
            int n0 = t * 8 + 2 * c;
            *(float2*)(sm + OFF_B + (sRow + r) * S + n0)     = make_float2(g0, g1);
            *(float2*)(sm + OFF_B + (sRow + r + 8) * S + n0) = make_float2(g2, g3);
        }
        os0 += __shfl_xor_sync(0xFFFFFFFFu, os0, 1);
        os0 += __shfl_xor_sync(0xFFFFFFFFu, os0, 2);
        os1 += __shfl_xor_sync(0xFFFFFFFFu, os1, 1);
        os1 += __shfl_xor_sync(0xFFFFFFFFu, os1, 2);
        if (c == 0) {
            out[(size_t)(tile * 128 + sRow + r) * 8 + d]     = os0 + bo_d;
            out[(size_t)(tile * 128 + sRow + r + 8) * 8 + d] = os1 + bo_d;
        }
    }
    __syncthreads();

    STAGE_TR(W2 + d * 4096);
    __syncthreads();

    // ---- bwd2: g(B) @ W2 -> *m1 -> A ----
    INIT_Z();
    gemm_mma<8, 8>(sm + OFF_B, sm + OFF_WHI, sm + OFF_WLO, sRow, r, c, acc);
    EPI_BWD(OFF_A, m1);
    __syncthreads();

    STAGE_TR(W1 + d * 4096);
    __syncthreads();

    // ---- bwd1: g2(A) @ W1 -> *m0 -> B ----
    INIT_Z();
    gemm_mma<8, 8>(sm + OFF_A, sm + OFF_WHI, sm + OFF_WLO, sRow, r, c, acc);
    EPI_BWD(OFF_B, m0);
    __syncthreads();

    // ---- stage W0^T for jac: rows n=0..16 = W0[:,n]; rows 17..23 zero ----
    for (int i = tid; i < 448; i += 256) {
        int row = 17 + i / 64, cc = i & 63;
        sm[OFF_WHI + row * S + cc] = 0.f;
        sm[OFF_WLO + row * S + cc] = 0.f;
    }
    for (int i = tid; i < 1088; i += 256) {
        int h = i / 17, nn = i - 17 * h;
        float v = W0[d * 1088 + i];
        float hh = uf(cvtt(v));
        sm[OFF_WHI + nn * S + h] = hh;
        sm[OFF_WLO + nn * S + h] = uf(cvtt(v - hh));
    }
    __syncthreads();

    // ---- jac: g1(B) @ W0 (NT=3, cols 0..16 valid) ----
    {
        float a3[12];
#pragma unroll
        for (int i = 0; i < 12; ++i) a3[i] = 0.f;
        gemm_mma<3, 8>(sm + OFF_B, sm + OFF_WHI, sm + OFF_WLO, sRow, r, c, a3);
        float* dst0 = out + 524416 + ((size_t)d * 65536 + tile * 128 + sRow + r) * 16;
        float* dst1 = dst0 + 8 * 16;
#pragma unroll
        for (int t = 0; t < 2; ++t) {
            int n0 = t * 8 + 2 * c;
            *(float2*)(dst0 + n0) = make_float2(a3[t * 4],     a3[t * 4 + 1]);
            *(float2*)(dst1 + n0) = make_float2(a3[t * 4 + 2], a3[t * 4 + 3]);
        }
        float jl = (c == 0) ? (logf(fabsf(a3[8])) + logf(fabsf(a3[10]))) : 0.f;
#pragma unroll
        for (int o = 16; o > 0; o >>= 1)
            jl += __shfl_xor_sync(0xFFFFFFFFu, jl, o);
        if (lane == 0) sm[OFF_J + warp] = jl;
    }
    __syncthreads();

    // ---- publish partial; last block reduces logdet ----
    if (tid == 0) {
        float sj = 0.f;
#pragma unroll
        for (int q = 0; q < 8; ++q) sj += sm[OFF_J + q];
        g_partials[d * 512 + tile] = sj;
        __threadfence();
        u32 v = atomicAdd(&g_done, 1u);
        sm[OFF_FLAG] = (v == 4095u) ? 1.f : 0.f;
    }
    __syncthreads();
    if (sm[OFF_FLAG] != 0.f) {
        __threadfence();
        if (tid < 128) {
            const int b = tid;
            float s = 0.f;
#pragma unroll
            for (int dd = 0; dd < 8; ++dd)
#pragma unroll
                for (int q = 0; q < 4; ++q)
                    s += g_partials[dd * 512 + b * 4 + q];
            out[524288 + b] = s;
        }
        if (tid == 0) g_done = 0;
    }
}

extern "C" void kernel_launch(void* const* d_in, const int* in_sizes, int n_in,
                              void* d_out, int out_size) {
    const float* x  = (const float*)d_in[0];
    const float* W0 = (const float*)d_in[1];
    const float* b0 = (const float*)d_in[2];
    const float* W1 = (const float*)d_in[3];
    const float* b1 = (const float*)d_in[4];
    const float* W2 = (const float*)d_in[5];
    const float* b2 = (const float*)d_in[6];
    const float* Wo = (const float*)d_in[7];
    const float* bo = (const float*)d_in[8];
    float* out = (float*)d_out;

    cudaFuncSetAttribute(mlp_mma_kernel,
                         cudaFuncAttributeMaxDynamicSharedMemorySize, SMEM_BYTES);
    dim3 grid(512, 8);
    mlp_mma_kernel<<<grid, 256, SMEM_BYTES>>>(x, W0, b0, W1, b1, W2, b2, Wo, bo, out);
}